// round 3
// baseline (speedup 1.0000x reference)
#include <cuda_runtime.h>

#define BB 2
#define DD 64
#define HH 128
#define WW 128
#define NS (BB*DD)      // 128 slices
#define QPS 4           // quarters per slice
#define NBLK (NS*QPS)   // 512 blocks, 32 rows each
#define BROWS 32
#define SEGR 16         // owned rows per vertical segment (2 segments x 128 cols)
#define PAD 10
#define STRW 148        // u16 stride per shared row (128 + 2*10)

__device__ volatile float g_part_sum[NBLK];
__device__ volatile int   g_part_cnt[NBLK];
__device__ volatile int   g_part_fg[NBLK];
__device__ unsigned int   g_done = 0;

// One block per (slice, quarter). Cap=10 bounds the vertical dependency range,
// so each 16-row column segment is exact with a 10-row halo re-scan. df|db
// packed in one u16; after the backward pass the word holds (f^2 | b^2<<8).
// Horizontal: s binary => exactly one polarity nonzero per pixel => one
// 19-candidate window min on the selected byte plane. Finalize fused via
// last-block atomic counter (self-resetting, graph-safe).
__global__ __launch_bounds__(256)
void edt_kernel(const float* __restrict__ yp, const float* __restrict__ yt,
                float* __restrict__ out)
{
    __shared__ unsigned short g2[BROWS][STRW];
    __shared__ float wsum[8];
    __shared__ int   wcnt[8];
    __shared__ int   s_islast;
    __shared__ unsigned s_fgw[4];
    __shared__ int s_first[BB], s_last[BB];

    const int blk   = blockIdx.x;
    const int slice = blk >> 2;
    const int R0    = (blk & 3) * BROWS;   // global first row of this block
    const int t     = threadIdx.x;
    const int lane  = t & 31, warp = t >> 5;
    const float* yps = yp + (size_t)slice * HH * WW;
    const float* yts = yt + (size_t)slice * HH * WW;

    // pad columns = (100,100): 100 + d^2 never beats an in-window candidate below the clamp
    for (int i = t; i < BROWS * 2 * PAD; i += 256) {
        int r = i / (2 * PAD);
        int p = i - r * 2 * PAD;
        int c = (p < PAD) ? p : (p + WW);
        g2[r][c] = 0x6464;
    }

    // ---------------- vertical pass (2 segments x 128 columns) ----------------
    const int col = t & (WW - 1);
    const int seg = t >> 7;          // 0 or 1
    const int r0  = R0 + seg * SEGR; // global first owned row
    const int lr0 = seg * SEGR;      // local row offset

    int fg = 0;
    int df = 10, db = 10;
    if (r0 > 0) {                    // 10-row warm-up halo above (uniform per warp)
        #pragma unroll
        for (int k = 10; k >= 1; k--) {
            float v = __ldg(&yps[(r0 - k) * WW + col]);
            int sv = v > 0.7f;
            fg |= sv;
            df = sv ? min(df + 1, 10) : 0;
            db = sv ? 0 : min(db + 1, 10);
        }
    }
    #pragma unroll
    for (int i = 0; i < SEGR; i++) {
        float v = __ldg(&yps[(r0 + i) * WW + col]);
        int sv = v > 0.7f;
        fg |= sv;
        df = sv ? min(df + 1, 10) : 0;      // edt(s): zeros where s==0
        db = sv ? 0 : min(db + 1, 10);      // edt(1-s): zeros where s==1
        g2[lr0 + i][col + PAD] = (unsigned short)(df | (db << 8));
    }
    df = 10; db = 10;
    if (r0 + SEGR < HH) {            // 10-row warm-up halo below
        #pragma unroll
        for (int k = 10; k >= 1; k--) {
            float v = __ldg(&yps[(r0 + SEGR - 1 + k) * WW + col]);
            int sv = v > 0.7f;
            df = sv ? min(df + 1, 10) : 0;
            db = sv ? 0 : min(db + 1, 10);
        }
    }
    #pragma unroll
    for (int i = SEGR - 1; i >= 0; i--) {
        unsigned int w = g2[lr0 + i][col + PAD];
        int fo = (int)(w & 255u), bo = (int)(w >> 8);
        int sv = fo > 0;                      // recover s from forward value
        df = sv ? min(df + 1, 10) : 0;
        db = sv ? 0 : min(db + 1, 10);
        int f = min(fo, df), b = min(bo, db);
        g2[lr0 + i][col + PAD] = (unsigned short)((f * f) | ((b * b) << 8));
    }
    int anyfg = __syncthreads_or(fg);

    // ---------------- horizontal pass: warp-per-row-group, coalesced y_true ----
    float acc = 0.0f; int cnt = 0;
    #pragma unroll
    for (int rr = 0; rr < 4; rr++) {
        int row = warp * 4 + rr;
        const unsigned char* rowb = (const unsigned char*)&g2[row][0];
        const float* yrow = yts + (size_t)(R0 + row) * WW;
        #pragma unroll
        for (int m = 0; m < 4; m++) {
            int j = lane + m * 32;
            int base = (j + PAD) * 2;
            unsigned int w = *(const unsigned short*)(rowb + base);
            int fo = (int)(w & 255u);
            int sel = (fo > 0) ? 0 : 1;              // pick nonzero polarity plane
            int mn  = (fo > 0) ? fo : (int)(w >> 8); // d=0 candidate
            const unsigned char* p = rowb + sel;
            #pragma unroll
            for (int d = 1; d <= 9; d++) {
                int c2 = d * d;
                mn = min(mn, (int)p[base + 2 * d] + c2);
                mn = min(mn, (int)p[base - 2 * d] + c2);
            }
            float c = fminf(sqrtf((float)mn), 10.0f);
            float y = __ldg(&yrow[j]);
            cnt += (y != 0.0f) ? 1 : 0;
            acc += c * y;
        }
    }

    // ---------------- block reduction ----------------
    #pragma unroll
    for (int o = 16; o > 0; o >>= 1) {
        acc += __shfl_down_sync(0xffffffffu, acc, o);
        cnt += __shfl_down_sync(0xffffffffu, cnt, o);
    }
    if (lane == 0) { wsum[warp] = acc; wcnt[warp] = cnt; }
    __syncthreads();
    if (t == 0) {
        float s = 0.0f; int c = 0;
        #pragma unroll
        for (int i = 0; i < 8; i++) { s += wsum[i]; c += wcnt[i]; }
        g_part_sum[blk] = s;
        g_part_cnt[blk] = c;
        g_part_fg[blk]  = anyfg;
        __threadfence();
        unsigned old = atomicAdd(&g_done, 1u);
        s_islast = (old == NBLK - 1u);
        if (s_islast) g_done = 0;   // self-reset for graph replay
    }
    __syncthreads();
    if (!s_islast) return;

    // ---------------- fused finalize (last block only) ----------------
    __threadfence();
    int f = 0;
    if (t < NS) f = (g_part_fg[QPS * t] | g_part_fg[QPS * t + 1] |
                     g_part_fg[QPS * t + 2] | g_part_fg[QPS * t + 3]);
    unsigned bal = __ballot_sync(0xffffffffu, f != 0);
    if (t < NS && lane == 0) s_fgw[warp] = bal;
    __syncthreads();
    if (t < BB) {
        unsigned long long m = (unsigned long long)s_fgw[2 * t] |
                               ((unsigned long long)s_fgw[2 * t + 1] << 32);
        s_first[t] = m ? (__ffsll((long long)m) - 1) : 0;      // argmax(all-false)=0
        s_last[t]  = m ? (63 - __clzll((long long)m)) : (DD - 1);
    }
    __syncthreads();
    float ms = 0.0f; int mc = 0;
    #pragma unroll
    for (int q = 0; q < 2; q++) {
        int p  = t + q * 256;            // part index (NBLK=512, 256 threads)
        int sl = p >> 2;                 // slice
        int b  = sl >> 6;
        int d  = sl & (DD - 1);
        int in = (d >= s_first[b]) && (d <= s_last[b]);
        ms += in ? g_part_sum[p] : 0.0f;
        mc += g_part_cnt[p];
    }
    #pragma unroll
    for (int o = 16; o > 0; o >>= 1) {
        ms += __shfl_down_sync(0xffffffffu, ms, o);
        mc += __shfl_down_sync(0xffffffffu, mc, o);
    }
    if (lane == 0) { wsum[warp] = ms; wcnt[warp] = mc; }
    __syncthreads();
    if (t == 0) {
        float s = 0.0f; long long c = 0;
        #pragma unroll
        for (int i = 0; i < 8; i++) { s += wsum[i]; c += wcnt[i]; }
        out[0] = s / (float)c;
    }
}

extern "C" void kernel_launch(void* const* d_in, const int* in_sizes, int n_in,
                              void* d_out, int out_size)
{
    const float* yp = (const float*)d_in[0];
    const float* yt = (const float*)d_in[1];
    float* out = (float*)d_out;
    edt_kernel<<<NBLK, 256>>>(yp, yt, out);
}

// round 4
// speedup vs baseline: 1.1226x; 1.1226x over previous
#include <cuda_runtime.h>

#define BB 2
#define DD 64
#define HH 128
#define WW 128
#define NS (BB*DD)      // 128 slices
#define QPS 8           // parts per slice
#define NBLK (NS*QPS)   // 1024 blocks, 16 rows each
#define BROWS 16
#define SEGR 8          // owned rows per vertical segment (2 segments x 128 cols)
#define PAD 10
#define STRW 148        // u16 stride per shared row (128 + 2*10)

__device__ volatile float g_part_sum[NBLK];
__device__ volatile float g_part_cnt[NBLK];
__device__ volatile int   g_part_fg[NBLK];
__device__ unsigned int   g_done = 0;

__device__ __forceinline__ float fast_sqrt(float x) {
    float r; asm("sqrt.approx.f32 %0, %1;" : "=f"(r) : "f"(x)); return r;
}

// One block per (slice, eighth). Cap=10 bounds the vertical dependency range:
// the 10-row warm-up halos collapse to bitmask ctz (exact under the cap).
// Horizontal: s binary => exactly one polarity nonzero per pixel => one
// 19-candidate window min on the selected byte plane; distances >=10 clamp.
// Finalize fused via last-block atomic counter (self-resetting, graph-safe).
__global__ __launch_bounds__(256, 6)
void edt_kernel(const float* __restrict__ yp, const float* __restrict__ yt,
                float* __restrict__ out)
{
    __shared__ unsigned short g2[BROWS][STRW];
    __shared__ float wsum[8], wcnt[8];
    __shared__ int s_islast;
    __shared__ unsigned s_fgw[4];
    __shared__ int s_first[BB], s_last[BB];

    const int blk   = blockIdx.x;
    const int slice = blk >> 3;
    const int R0    = (blk & 7) * BROWS;
    const int t     = threadIdx.x;
    const int lane  = t & 31, warp = t >> 5;
    const float* yps = yp + (size_t)slice * HH * WW;
    const float* yts = yt + (size_t)slice * HH * WW;

    // pad columns = (100,100): 100 + d^2 never beats an in-window candidate below the clamp
    for (int i = t; i < BROWS * 2 * PAD; i += 256) {
        int r = i / (2 * PAD);
        int p = i - r * (2 * PAD);
        int c = (p < PAD) ? p : (p + WW);
        g2[r][c] = 0x6464;
    }

    // ---------------- vertical pass (2 segments x 128 columns) ----------------
    const int col = t & (WW - 1);
    const int seg = t >> 7;
    const int r0  = R0 + seg * SEGR;
    const int lr0 = seg * SEGR;

    int fg = 0;
    int df = 10, db = 10;
    if (r0 > 0) {                     // top halo: bitmask init (exact under cap)
        unsigned m = 0;
        #pragma unroll
        for (int k = 0; k < 10; k++) {
            float v = __ldg(&yps[(r0 - 10 + k) * WW + col]);
            m |= (v > 0.7f ? 1u : 0u) << (9 - k);   // bit0 = row r0-1
        }
        fg |= (m != 0);
        unsigned z = (~m) & 0x3FFu;
        df = z ? (__ffs(z) - 1) : 10;
        db = m ? (__ffs(m) - 1) : 10;
    }

    float ov[SEGR];
    #pragma unroll
    for (int i = 0; i < SEGR; i++) ov[i] = __ldg(&yps[(r0 + i) * WW + col]);

    int pfb[SEGR];                    // packed df | db<<8, kept in regs
    #pragma unroll
    for (int i = 0; i < SEGR; i++) {
        int sv = ov[i] > 0.7f;
        fg |= sv;
        df = sv ? min(df + 1, 10) : 0;    // edt(s): zeros where s==0
        db = sv ? 0 : min(db + 1, 10);    // edt(1-s): zeros where s==1
        pfb[i] = df | (db << 8);
    }

    df = 10; db = 10;
    {                                 // bottom halo: bitmask init
        int n = HH - (r0 + SEGR);
        if (n > 10) n = 10;
        if (n > 0) {
            unsigned m = 0;
            #pragma unroll
            for (int k = 0; k < 10; k++) {
                if (k < n) {
                    float v = __ldg(&yps[(r0 + SEGR + k) * WW + col]);
                    m |= (v > 0.7f ? 1u : 0u) << k;   // bit0 = row r0+SEGR
                }
            }
            fg |= (m != 0);
            unsigned z = (~m) & ((1u << n) - 1u);
            df = z ? (__ffs(z) - 1) : 10;
            db = m ? (__ffs(m) - 1) : 10;
        }
    }
    #pragma unroll
    for (int i = SEGR - 1; i >= 0; i--) {
        int fo = pfb[i] & 255, bo = pfb[i] >> 8;
        int sv = fo > 0;
        df = sv ? min(df + 1, 10) : 0;
        db = sv ? 0 : min(db + 1, 10);
        int f = min(fo, df), b = min(bo, db);
        g2[lr0 + i][col + PAD] = (unsigned short)((f * f) | ((b * b) << 8));
    }
    int anyfg = __syncthreads_or(fg);

    // ---------------- horizontal pass: warp -> 2 rows, coalesced y_true -------
    float acc = 0.0f, accy = 0.0f;
    #pragma unroll
    for (int rr = 0; rr < 2; rr++) {
        int row = warp * 2 + rr;
        const unsigned char* rowb = (const unsigned char*)&g2[row][0];
        const float* yrow = yts + (size_t)(R0 + row) * WW;
        #pragma unroll
        for (int m = 0; m < 4; m++) {
            int j = lane + m * 32;
            int base = (j + PAD) * 2;
            unsigned w = *(const unsigned short*)(rowb + base);
            int fo = (int)(w & 255u);
            int sel = (fo > 0) ? 0 : 1;               // pick nonzero polarity plane
            int mn  = (fo > 0) ? fo : (int)(w >> 8);  // d=0 candidate
            const unsigned char* p = rowb + sel;
            #pragma unroll
            for (int d = 1; d <= 9; d++) {
                int c2 = d * d;
                mn = min(mn, (int)p[base + 2 * d] + c2);
                mn = min(mn, (int)p[base - 2 * d] + c2);
            }
            float c = fminf(fast_sqrt((float)mn), 10.0f);
            float y = __ldg(&yrow[j]);
            acc  += c * y;
            accy += y;                // y in {0,1}: count == sum
        }
    }

    // ---------------- block reduction ----------------
    #pragma unroll
    for (int o = 16; o > 0; o >>= 1) {
        acc  += __shfl_down_sync(0xffffffffu, acc,  o);
        accy += __shfl_down_sync(0xffffffffu, accy, o);
    }
    if (lane == 0) { wsum[warp] = acc; wcnt[warp] = accy; }
    __syncthreads();
    if (t == 0) {
        float s = 0.0f, c = 0.0f;
        #pragma unroll
        for (int i = 0; i < 8; i++) { s += wsum[i]; c += wcnt[i]; }
        g_part_sum[blk] = s;
        g_part_cnt[blk] = c;
        g_part_fg[blk]  = anyfg;
        __threadfence();
        unsigned old = atomicAdd(&g_done, 1u);
        s_islast = (old == NBLK - 1u);
        if (s_islast) g_done = 0;   // self-reset for graph replay
    }
    __syncthreads();
    if (!s_islast) return;

    // ---------------- fused finalize (last block only) ----------------
    __threadfence();
    int f = 0;
    if (t < NS) {
        #pragma unroll
        for (int q = 0; q < QPS; q++) f |= g_part_fg[QPS * t + q];
    }
    unsigned bal = __ballot_sync(0xffffffffu, f != 0);
    if (t < NS && lane == 0) s_fgw[warp] = bal;
    __syncthreads();
    if (t < BB) {
        unsigned long long m = (unsigned long long)s_fgw[2 * t] |
                               ((unsigned long long)s_fgw[2 * t + 1] << 32);
        s_first[t] = m ? (__ffsll((long long)m) - 1) : 0;      // argmax(all-false)=0
        s_last[t]  = m ? (63 - __clzll((long long)m)) : (DD - 1);
    }
    __syncthreads();
    float ms = 0.0f, mc = 0.0f;
    #pragma unroll
    for (int q = 0; q < 4; q++) {
        int p  = t + q * 256;            // part index (NBLK=1024)
        int sl = p >> 3;
        int b  = sl >> 6;
        int d  = sl & (DD - 1);
        int in = (d >= s_first[b]) && (d <= s_last[b]);
        ms += in ? g_part_sum[p] : 0.0f;
        mc += g_part_cnt[p];
    }
    #pragma unroll
    for (int o = 16; o > 0; o >>= 1) {
        ms += __shfl_down_sync(0xffffffffu, ms, o);
        mc += __shfl_down_sync(0xffffffffu, mc, o);
    }
    if (lane == 0) { wsum[warp] = ms; wcnt[warp] = mc; }
    __syncthreads();
    if (t == 0) {
        float s = 0.0f, c = 0.0f;
        #pragma unroll
        for (int i = 0; i < 8; i++) { s += wsum[i]; c += wcnt[i]; }
        out[0] = s / c;
    }
}

extern "C" void kernel_launch(void* const* d_in, const int* in_sizes, int n_in,
                              void* d_out, int out_size)
{
    const float* yp = (const float*)d_in[0];
    const float* yt = (const float*)d_in[1];
    float* out = (float*)d_out;
    edt_kernel<<<NBLK, 256>>>(yp, yt, out);
}